// round 15
// baseline (speedup 1.0000x reference)
#include <cuda_runtime.h>

// Problem constants
#define B_    8
#define K_    64
#define L_    1024
#define CP_   32
#define CSA_  16
#define NOC1  256
#define K1    576          // K_*G2_
#define VPAD  36
#define EPAD  36
#define YPAD  28

typedef unsigned long long ull;

#define FFMA2(acc, a, b) asm("fma.rn.f32x2 %0, %1, %2, %0;" : "+l"(acc) : "l"(a), "l"(b))
#define MUL2(dst, a, b)  asm("mul.rn.f32x2 %0, %1, %2;" : "=l"(dst) : "l"(a), "l"(b))
#define ADD2(dst, a, b)  asm("add.rn.f32x2 %0, %1, %2;" : "=l"(dst) : "l"(a), "l"(b))
#define UNPACK2(lo, hi, v) asm("mov.b64 {%0, %1}, %2;" : "=f"(lo), "=f"(hi) : "l"(v))

#define MMA_TF32(c, au, b0, b1) \
    asm("mma.sync.aligned.m16n8k8.row.col.f32.tf32.tf32.f32 " \
        "{%0,%1,%2,%3},{%4,%5,%6,%7},{%8,%9},{%0,%1,%2,%3};" \
        : "+f"((c)[0]), "+f"((c)[1]), "+f"((c)[2]), "+f"((c)[3]) \
        : "r"((au).x), "r"((au).y), "r"((au).z), "r"((au).w), "r"(b0), "r"(b1))

__device__ __forceinline__ float t32hi(float x) {
    return __uint_as_float(__float_as_uint(x) & 0xFFFFE000u);
}

// Scratch (allocation-free: device globals)
__device__ float g_yq[B_ * L_ * NOC1];
__device__ float g_w1f[2 * 16 * 72 * 128];
__device__ float g_w2f[2 * 16 * 3 * 128];

// ---------------------------------------------------------------------------
__global__ void prep_kernel(const float* __restrict__ w1, const float* __restrict__ w2) {
    int idx = blockIdx.x * 256 + threadIdx.x;
    if (idx < 2 * 16 * 72 * 128) {
        int i    = idx & 3;
        int lane = (idx >> 2) & 31;
        int rest = idx >> 7;
        int kc    = rest % 72;
        int mtf   = (rest / 72) & 15;
        int split = rest / 1152;
        int group = lane >> 2, tid4 = lane & 3;
        int row = mtf * 16 + ((i & 1) << 3) + group;
        int col = kc * 8 + ((i >> 1) << 2) + tid4;
        float val = w1[row * K1 + col];
        float hi = t32hi(val);
        g_w1f[idx] = split ? (val - hi) : hi;
    }
    if (idx < 2 * 16 * 3 * 128) {
        int i    = idx & 3;
        int lane = (idx >> 2) & 31;
        int rest = idx >> 7;
        int k    = rest % 3;
        int mt   = (rest / 3) & 15;
        int split = rest / 48;
        int group = lane >> 2, tid4 = lane & 3;
        int row = ((i & 1) << 3) + group;
        int col = ((i >> 1) << 2) + tid4;
        float val = w2[(mt * 16 + row) * 24 + k * 8 + col];
        float hi = t32hi(val);
        g_w2f[idx] = split ? (val - hi) : hi;
    }
}

// ---------------------------------------------------------------------------
// Kernel 1: conv1 via tensor cores (R13-verified, unchanged)
// ---------------------------------------------------------------------------
__global__ __launch_bounds__(256) void conv1_mma_kernel(
    const float* __restrict__ x, const float* __restrict__ b1)
{
    __shared__ __align__(16) float sbuf[32 * 264];
    __shared__ float b1s[NOC1];
    float (*xh)[48]  = (float(*)[48])sbuf;
    float (*xl)[48]  = (float(*)[48])(sbuf + 64 * 48);
    float (*ysh)[264] = (float(*)[264])sbuf;

    const int b  = blockIdx.y;
    const int l0 = blockIdx.x * 32;
    const int t  = threadIdx.x;

    b1s[t] = b1[t];
    for (int i = t; i < K_ * 40; i += 256) {
        int ic = i / 40, j = i - ic * 40;
        int l = l0 - 4 + j;
        float v = (l >= 0 && l < L_) ? x[(b * K_ + ic) * L_ + l] : 0.f;
        float hi = t32hi(v);
        xh[ic][j] = hi;
        xl[ic][j] = v - hi;
    }
    __syncthreads();

    const int wid = t >> 5, lane = t & 31;
    const int group = lane >> 2, tid4 = lane & 3;

    float c[2][4][4];
#pragma unroll
    for (int mt = 0; mt < 2; mt++)
#pragma unroll
        for (int nt = 0; nt < 4; nt++)
#pragma unroll
            for (int i = 0; i < 4; i++) c[mt][nt][i] = 0.f;

    const float* xbh = &xh[0][0];
    const float* xbl = &xl[0][0];
    const float* wf0 = g_w1f + ((wid * 2 + 0) * 72) * 128 + lane * 4;
    const float* wf1 = g_w1f + ((wid * 2 + 1) * 72) * 128 + lane * 4;
    const float* wg0 = g_w1f + ((16 + wid * 2 + 0) * 72) * 128 + lane * 4;
    const float* wg1 = g_w1f + ((16 + wid * 2 + 1) * 72) * 128 + lane * 4;

    {
        int tt0 = tid4,     off0 = tid4;
        int tt1 = tid4 + 4, off1 = tid4 + 4;
        for (int kc = 0; kc < 72; kc++) {
            uint4 ah0 = *(const uint4*)(wf0 + kc * 128);
            uint4 ah1 = *(const uint4*)(wf1 + kc * 128);
            uint4 al0 = *(const uint4*)(wg0 + kc * 128);
            uint4 al1 = *(const uint4*)(wg1 + kc * 128);
            unsigned bb0[4], bb1[4];
#pragma unroll
            for (int nt = 0; nt < 4; nt++) {
                bb0[nt] = __float_as_uint(xbh[off0 + nt * 8 + group]);
                bb1[nt] = __float_as_uint(xbh[off1 + nt * 8 + group]);
            }
#pragma unroll
            for (int nt = 0; nt < 4; nt++) {
                MMA_TF32(c[0][nt], ah0, bb0[nt], bb1[nt]);
                MMA_TF32(c[1][nt], ah1, bb0[nt], bb1[nt]);
            }
#pragma unroll
            for (int nt = 0; nt < 4; nt++) {
                MMA_TF32(c[0][nt], al0, bb0[nt], bb1[nt]);
                MMA_TF32(c[1][nt], al1, bb0[nt], bb1[nt]);
            }
            tt0 += 8; if (tt0 >= 9) { tt0 -= 9; off0 += 47; } else off0 += 8;
            tt1 += 8; if (tt1 >= 9) { tt1 -= 9; off1 += 47; } else off1 += 8;
        }
    }
    {
        int tt0 = tid4,     off0 = tid4;
        int tt1 = tid4 + 4, off1 = tid4 + 4;
        for (int kc = 0; kc < 72; kc++) {
            uint4 ah0 = *(const uint4*)(wf0 + kc * 128);
            uint4 ah1 = *(const uint4*)(wf1 + kc * 128);
            unsigned bb0[4], bb1[4];
#pragma unroll
            for (int nt = 0; nt < 4; nt++) {
                bb0[nt] = __float_as_uint(xbl[off0 + nt * 8 + group]);
                bb1[nt] = __float_as_uint(xbl[off1 + nt * 8 + group]);
            }
#pragma unroll
            for (int nt = 0; nt < 4; nt++) {
                MMA_TF32(c[0][nt], ah0, bb0[nt], bb1[nt]);
                MMA_TF32(c[1][nt], ah1, bb0[nt], bb1[nt]);
            }
            tt0 += 8; if (tt0 >= 9) { tt0 -= 9; off0 += 47; } else off0 += 8;
            tt1 += 8; if (tt1 >= 9) { tt1 -= 9; off1 += 47; } else off1 += 8;
        }
    }
    __syncthreads();

#pragma unroll
    for (int mt = 0; mt < 2; mt++)
#pragma unroll
        for (int nt = 0; nt < 4; nt++)
#pragma unroll
            for (int i = 0; i < 4; i++) {
                int oc   = wid * 32 + mt * 16 + ((i >> 1) << 3) + group;
                int lloc = nt * 8 + tid4 * 2 + (i & 1);
                ysh[lloc][oc] = c[mt][nt][i] + b1s[oc];
            }
    __syncthreads();

    for (int g = t; g < 1024; g += 256) {
        int lloc = g >> 5, cp = g & 31;
        float4 a  = *(const float4*)&ysh[lloc][cp * 8];
        float4 c4 = *(const float4*)&ysh[lloc][cp * 8 + 4];
        float sq = (a.x * a.x + a.y * a.y) + (a.z * a.z + a.w * a.w)
                 + (c4.x * c4.x + c4.y * c4.y) + (c4.z * c4.z + c4.w * c4.w);
        float scale = sq / (1.f + sq) * rsqrtf(sq + 1e-8f);
        a.x *= scale; a.y *= scale; a.z *= scale; a.w *= scale;
        c4.x *= scale; c4.y *= scale; c4.z *= scale; c4.w *= scale;
        float* dst = &g_yq[((size_t)(b * L_ + l0 + lloc)) * NOC1 + cp * 8];
        *(float4*)dst       = a;
        *(float4*)(dst + 4) = c4;
    }
}

// ---------------------------------------------------------------------------
// Kernel 2: conv2 via tensor cores + routing. OCCUPANCY-TUNED (target 5 CTA/SM):
// y panels unioned with efT/sinv/vsh (y dead after MMA); a-frags loaded per-k;
// bias via direct __ldg. Logic identical to R13.
// ---------------------------------------------------------------------------
__global__ __launch_bounds__(256, 5) void conv2_route_kernel(
    const float* __restrict__ b2, float* __restrict__ out)
{
    __shared__ __align__(16) float smu[2 * CP_ * YPAD];   // yph|ypl, then efT/sinv/vsh
    __shared__ __align__(16) float Vs[16][16][VPAD];

    float (*yph)[YPAD] = (float(*)[YPAD])smu;
    float (*ypl)[YPAD] = (float(*)[YPAD])(smu + CP_ * YPAD);
    float (*efT)[EPAD] = (float(*)[EPAD])smu;              // union (post-MMA)
    float* sinv        = smu + 576;                        // 16B-aligned
    float (*vsh)[16]   = (float(*)[16])(smu + 608);        // 16B-aligned

    const int bl = blockIdx.x;
    const int l  = bl & (L_ - 1);
    const int t  = threadIdx.x;
    const int wid   = t >> 5;
    const int lane  = t & 31;
    const int group = lane >> 2;
    const int tid4  = lane & 3;

    {
        const float* base = g_yq + (size_t)bl * NOC1;
        const int cp_i = t >> 3, j_i = t & 7;
#pragma unroll
        for (int dh = 0; dh < 3; dh++) {
            float val = 0.f;
            if ((dh == 1) || (dh == 0 && l > 0) || (dh == 2 && l < L_ - 1))
                val = base[t + (dh - 1) * NOC1];
            float hi = t32hi(val);
            yph[cp_i][dh * 8 + j_i] = hi;
            ypl[cp_i][dh * 8 + j_i] = val - hi;
        }
    }
    __syncthreads();

    // c-frags, bias init via direct ldg
    float c[2][4][4];
#pragma unroll
    for (int mt = 0; mt < 2; mt++) {
        float bv0 = __ldg(&b2[wid * 32 + mt * 16 + group]);
        float bv1 = __ldg(&b2[wid * 32 + mt * 16 + 8 + group]);
#pragma unroll
        for (int nt = 0; nt < 4; nt++) {
            c[mt][nt][0] = bv0; c[mt][nt][1] = bv0;
            c[mt][nt][2] = bv1; c[mt][nt][3] = bv1;
        }
    }

    // Terms 1,2: w_hi x y_hi, w_hi x y_lo — a-frags loaded per k-step
#pragma unroll
    for (int pass = 0; pass < 2; pass++) {
        const float (*yp)[YPAD] = pass ? ypl : yph;
#pragma unroll
        for (int k = 0; k < 3; k++) {
            uint4 a0 = *(const uint4*)&g_w2f[(((wid * 2 + 0)) * 3 + k) * 128 + lane * 4];
            uint4 a1 = *(const uint4*)&g_w2f[(((wid * 2 + 1)) * 3 + k) * 128 + lane * 4];
#pragma unroll
            for (int nt = 0; nt < 4; nt++) {
                unsigned b0 = __float_as_uint(yp[nt * 8 + group][k * 8 + tid4]);
                unsigned b1 = __float_as_uint(yp[nt * 8 + group][k * 8 + tid4 + 4]);
                MMA_TF32(c[0][nt], a0, b0, b1);
                MMA_TF32(c[1][nt], a1, b0, b1);
            }
        }
    }
    // Term 3: w_lo x y_hi
#pragma unroll
    for (int k = 0; k < 3; k++) {
        uint4 a0 = *(const uint4*)&g_w2f[((16 + wid * 2 + 0) * 3 + k) * 128 + lane * 4];
        uint4 a1 = *(const uint4*)&g_w2f[((16 + wid * 2 + 1) * 3 + k) * 128 + lane * 4];
#pragma unroll
        for (int nt = 0; nt < 4; nt++) {
            unsigned b0 = __float_as_uint(yph[nt * 8 + group][k * 8 + tid4]);
            unsigned b1 = __float_as_uint(yph[nt * 8 + group][k * 8 + tid4 + 4]);
            MMA_TF32(c[0][nt], a0, b0, b1);
            MMA_TF32(c[1][nt], a1, b0, b1);
        }
    }

#pragma unroll
    for (int mt = 0; mt < 2; mt++) {
        int csaw = wid * 2 + mt;
#pragma unroll
        for (int nt = 0; nt < 4; nt++) {
            int cp0 = nt * 8 + tid4 * 2;
            *(float2*)&Vs[csaw][group][cp0]     = make_float2(c[mt][nt][0], c[mt][nt][1]);
            *(float2*)&Vs[csaw][group + 8][cp0] = make_float2(c[mt][nt][2], c[mt][nt][3]);
        }
    }
    __syncthreads();   // y panels dead from here; smu reused as efT/sinv/vsh

    const int csa = t >> 4;
    const int asa = t & 15;
    const ulonglong2* Vp = (const ulonglong2*)&Vs[csa][asa][0];

    float v;
    {
        const float4* vr = (const float4*)&Vs[csa][asa][0];
        float4 r0 = vr[0], r1 = vr[1], r2 = vr[2], r3 = vr[3];
        float4 r4 = vr[4], r5 = vr[5], r6 = vr[6], r7 = vr[7];
        float s0 = (r0.x + r0.y) + (r0.z + r0.w) + (r4.x + r4.y) + (r4.z + r4.w);
        float s1 = (r1.x + r1.y) + (r1.z + r1.w) + (r5.x + r5.y) + (r5.z + r5.w);
        float s2 = (r2.x + r2.y) + (r2.z + r2.w) + (r6.x + r6.y) + (r6.z + r6.w);
        float s3 = (r3.x + r3.y) + (r3.z + r3.w) + (r7.x + r7.y) + (r7.z + r7.w);
        float s = ((s0 + s1) + (s2 + s3)) * (1.f / 16.f);
        float sq = s * s;
        sq += __shfl_xor_sync(0xffffffffu, sq, 1);
        sq += __shfl_xor_sync(0xffffffffu, sq, 2);
        sq += __shfl_xor_sync(0xffffffffu, sq, 4);
        sq += __shfl_xor_sync(0xffffffffu, sq, 8);
        float scale = sq / (1.f + sq) * rsqrtf(sq + 1e-8f);
        v = s * scale;
    }
    vsh[csa][asa] = v;
    __syncthreads();

    const int cp_a = t & 31;
    const int cs0  = t >> 5;
    float blog0, blog1;
    {
        const float4* vpA = (const float4*)vsh[cs0];
        const float4* vpB = (const float4*)vsh[cs0 + 8];
        float4 vA0 = vpA[0], vA1 = vpA[1], vA2 = vpA[2], vA3 = vpA[3];
        float4 vB0 = vpB[0], vB1 = vpB[1], vB2 = vpB[2], vB3 = vpB[3];
        const float* VsA = &Vs[cs0][0][cp_a];
        const float* VsB = &Vs[cs0 + 8][0][cp_a];
        float p0, p1, q0, q1;
        p0  = VsA[0*VPAD]*vA0.x + VsA[1*VPAD]*vA0.y + VsA[2*VPAD]*vA0.z + VsA[3*VPAD]*vA0.w;
        p1  = VsA[4*VPAD]*vA1.x + VsA[5*VPAD]*vA1.y + VsA[6*VPAD]*vA1.z + VsA[7*VPAD]*vA1.w;
        p0 += VsA[8*VPAD]*vA2.x + VsA[9*VPAD]*vA2.y + VsA[10*VPAD]*vA2.z + VsA[11*VPAD]*vA2.w;
        p1 += VsA[12*VPAD]*vA3.x + VsA[13*VPAD]*vA3.y + VsA[14*VPAD]*vA3.z + VsA[15*VPAD]*vA3.w;
        q0  = VsB[0*VPAD]*vB0.x + VsB[1*VPAD]*vB0.y + VsB[2*VPAD]*vB0.z + VsB[3*VPAD]*vB0.w;
        q1  = VsB[4*VPAD]*vB1.x + VsB[5*VPAD]*vB1.y + VsB[6*VPAD]*vB1.z + VsB[7*VPAD]*vB1.w;
        q0 += VsB[8*VPAD]*vB2.x + VsB[9*VPAD]*vB2.y + VsB[10*VPAD]*vB2.z + VsB[11*VPAD]*vB2.w;
        q1 += VsB[12*VPAD]*vB3.x + VsB[13*VPAD]*vB3.y + VsB[14*VPAD]*vB3.z + VsB[15*VPAD]*vB3.w;
        blog0 = p0 + p1;
        blog1 = q0 + q1;
    }

#pragma unroll
    for (int r = 1; r < 3; r++) {
        efT[cs0][cp_a]     = __expf(blog0);
        efT[cs0 + 8][cp_a] = __expf(blog1);
        __syncthreads();
        if (t < CP_) {
            float u0 = 0.f, u1 = 0.f, u2 = 0.f, u3 = 0.f;
#pragma unroll
            for (int j2 = 0; j2 < CSA_; j2 += 4) {
                u0 += efT[j2][t];     u1 += efT[j2 + 1][t];
                u2 += efT[j2 + 2][t]; u3 += efT[j2 + 3][t];
            }
            sinv[t] = __fdividef(1.f, (u0 + u1) + (u2 + u3));
        }
        __syncthreads();

        ull s2a = 0ULL, s2b = 0ULL, s2c = 0ULL, s2d = 0ULL;
        const ulonglong2* efp = (const ulonglong2*)&efT[csa][0];
        const ulonglong2* svp = (const ulonglong2*)sinv;
#pragma unroll
        for (int q = 0; q < 8; q++) {
            ulonglong2 e2 = efp[q];
            ulonglong2 n2 = svp[q];
            ulonglong2 v2 = Vp[q];
            ull p0, p1;
            MUL2(p0, e2.x, n2.x);
            MUL2(p1, e2.y, n2.y);
            if (q & 1) {
                FFMA2(s2c, p0, v2.x);
                FFMA2(s2d, p1, v2.y);
            } else {
                FFMA2(s2a, p0, v2.x);
                FFMA2(s2b, p1, v2.y);
            }
        }
        ADD2(s2a, s2a, s2b);
        ADD2(s2c, s2c, s2d);
        ADD2(s2a, s2a, s2c);
        float lo, hi;
        UNPACK2(lo, hi, s2a);
        float s = lo + hi;

        float sq = s * s;
        sq += __shfl_xor_sync(0xffffffffu, sq, 1);
        sq += __shfl_xor_sync(0xffffffffu, sq, 2);
        sq += __shfl_xor_sync(0xffffffffu, sq, 4);
        sq += __shfl_xor_sync(0xffffffffu, sq, 8);
        float scale = sq / (1.f + sq) * rsqrtf(sq + 1e-8f);
        v = s * scale;

        if (r < 2) {
            vsh[csa][asa] = v;
            __syncthreads();
            const float4* vpA = (const float4*)vsh[cs0];
            const float4* vpB = (const float4*)vsh[cs0 + 8];
            float4 vA0 = vpA[0], vA1 = vpA[1], vA2 = vpA[2], vA3 = vpA[3];
            float4 vB0 = vpB[0], vB1 = vpB[1], vB2 = vpB[2], vB3 = vpB[3];
            const float* VsA = &Vs[cs0][0][cp_a];
            const float* VsB = &Vs[cs0 + 8][0][cp_a];
            float p0, p1, q0, q1;
            p0  = VsA[0*VPAD]*vA0.x + VsA[1*VPAD]*vA0.y + VsA[2*VPAD]*vA0.z + VsA[3*VPAD]*vA0.w;
            p1  = VsA[4*VPAD]*vA1.x + VsA[5*VPAD]*vA1.y + VsA[6*VPAD]*vA1.z + VsA[7*VPAD]*vA1.w;
            p0 += VsA[8*VPAD]*vA2.x + VsA[9*VPAD]*vA2.y + VsA[10*VPAD]*vA2.z + VsA[11*VPAD]*vA2.w;
            p1 += VsA[12*VPAD]*vA3.x + VsA[13*VPAD]*vA3.y + VsA[14*VPAD]*vA3.z + VsA[15*VPAD]*vA3.w;
            q0  = VsB[0*VPAD]*vB0.x + VsB[1*VPAD]*vB0.y + VsB[2*VPAD]*vB0.z + VsB[3*VPAD]*vB0.w;
            q1  = VsB[4*VPAD]*vB1.x + VsB[5*VPAD]*vB1.y + VsB[6*VPAD]*vB1.z + VsB[7*VPAD]*vB1.w;
            q0 += VsB[8*VPAD]*vB2.x + VsB[9*VPAD]*vB2.y + VsB[10*VPAD]*vB2.z + VsB[11*VPAD]*vB2.w;
            q1 += VsB[12*VPAD]*vB3.x + VsB[13*VPAD]*vB3.y + VsB[14*VPAD]*vB3.z + VsB[15*VPAD]*vB3.w;
            blog0 += p0 + p1;
            blog1 += q0 + q1;
        }
    }

    out[(size_t)bl * 256 + t] = v;
}

// ---------------------------------------------------------------------------
extern "C" void kernel_launch(void* const* d_in, const int* in_sizes, int n_in,
                              void* d_out, int out_size)
{
    const float* x  = (const float*)d_in[0];
    const float* w1 = (const float*)d_in[1];
    const float* b1 = (const float*)d_in[2];
    const float* w2 = (const float*)d_in[3];
    const float* b2 = (const float*)d_in[4];
    float* out = (float*)d_out;

    prep_kernel<<<1152, 256>>>(w1, w2);
    conv1_mma_kernel<<<dim3(L_ / 32, B_), 256>>>(x, b1);
    conv2_route_kernel<<<B_ * L_, 256>>>(b2, out);
}

// round 16
// speedup vs baseline: 1.5116x; 1.5116x over previous
#include <cuda_runtime.h>

// Problem constants
#define B_    8
#define K_    64
#define L_    1024
#define CP_   32
#define CSA_  16
#define NOC1  256
#define K1    576          // K_*G2_
#define VPAD  36
#define EPAD  36
#define YPAD  28

typedef unsigned long long ull;

#define FFMA2(acc, a, b) asm("fma.rn.f32x2 %0, %1, %2, %0;" : "+l"(acc) : "l"(a), "l"(b))
#define MUL2(dst, a, b)  asm("mul.rn.f32x2 %0, %1, %2;" : "=l"(dst) : "l"(a), "l"(b))
#define ADD2(dst, a, b)  asm("add.rn.f32x2 %0, %1, %2;" : "=l"(dst) : "l"(a), "l"(b))
#define UNPACK2(lo, hi, v) asm("mov.b64 {%0, %1}, %2;" : "=f"(lo), "=f"(hi) : "l"(v))

#define MMA_TF32(c, au, b0, b1) \
    asm("mma.sync.aligned.m16n8k8.row.col.f32.tf32.tf32.f32 " \
        "{%0,%1,%2,%3},{%4,%5,%6,%7},{%8,%9},{%0,%1,%2,%3};" \
        : "+f"((c)[0]), "+f"((c)[1]), "+f"((c)[2]), "+f"((c)[3]) \
        : "r"((au).x), "r"((au).y), "r"((au).z), "r"((au).w), "r"(b0), "r"(b1))

__device__ __forceinline__ float t32hi(float x) {
    return __uint_as_float(__float_as_uint(x) & 0xFFFFE000u);
}

// Scratch (allocation-free: device globals)
__device__ float g_yq[B_ * L_ * NOC1];
__device__ float g_w1f[2 * 16 * 72 * 128];
__device__ float g_w2f[2 * 16 * 3 * 128];

// ---------------------------------------------------------------------------
// Prep: build tf32 hi/lo weight fragments for conv1 and conv2
// ---------------------------------------------------------------------------
__global__ void prep_kernel(const float* __restrict__ w1, const float* __restrict__ w2) {
    int idx = blockIdx.x * 256 + threadIdx.x;
    if (idx < 2 * 16 * 72 * 128) {
        int i    = idx & 3;
        int lane = (idx >> 2) & 31;
        int rest = idx >> 7;
        int kc    = rest % 72;
        int mtf   = (rest / 72) & 15;
        int split = rest / 1152;
        int group = lane >> 2, tid4 = lane & 3;
        int row = mtf * 16 + ((i & 1) << 3) + group;
        int col = kc * 8 + ((i >> 1) << 2) + tid4;
        float val = w1[row * K1 + col];
        float hi = t32hi(val);
        g_w1f[idx] = split ? (val - hi) : hi;
    }
    if (idx < 2 * 16 * 3 * 128) {
        int i    = idx & 3;
        int lane = (idx >> 2) & 31;
        int rest = idx >> 7;
        int k    = rest % 3;
        int mt   = (rest / 3) & 15;
        int split = rest / 48;
        int group = lane >> 2, tid4 = lane & 3;
        int row = ((i & 1) << 3) + group;
        int col = ((i >> 1) << 2) + tid4;
        float val = w2[(mt * 16 + row) * 24 + k * 8 + col];
        float hi = t32hi(val);
        g_w2f[idx] = split ? (val - hi) : hi;
    }
}

// ---------------------------------------------------------------------------
// Kernel 1: conv1 via tensor cores (R13-verified, unchanged)
// ---------------------------------------------------------------------------
__global__ __launch_bounds__(256) void conv1_mma_kernel(
    const float* __restrict__ x, const float* __restrict__ b1)
{
    __shared__ __align__(16) float sbuf[32 * 264];
    __shared__ float b1s[NOC1];
    float (*xh)[48]  = (float(*)[48])sbuf;
    float (*xl)[48]  = (float(*)[48])(sbuf + 64 * 48);
    float (*ysh)[264] = (float(*)[264])sbuf;

    const int b  = blockIdx.y;
    const int l0 = blockIdx.x * 32;
    const int t  = threadIdx.x;

    b1s[t] = b1[t];
    for (int i = t; i < K_ * 40; i += 256) {
        int ic = i / 40, j = i - ic * 40;
        int l = l0 - 4 + j;
        float v = (l >= 0 && l < L_) ? x[(b * K_ + ic) * L_ + l] : 0.f;
        float hi = t32hi(v);
        xh[ic][j] = hi;
        xl[ic][j] = v - hi;
    }
    __syncthreads();

    const int wid = t >> 5, lane = t & 31;
    const int group = lane >> 2, tid4 = lane & 3;

    float c[2][4][4];
#pragma unroll
    for (int mt = 0; mt < 2; mt++)
#pragma unroll
        for (int nt = 0; nt < 4; nt++)
#pragma unroll
            for (int i = 0; i < 4; i++) c[mt][nt][i] = 0.f;

    const float* xbh = &xh[0][0];
    const float* xbl = &xl[0][0];
    const float* wf0 = g_w1f + ((wid * 2 + 0) * 72) * 128 + lane * 4;
    const float* wf1 = g_w1f + ((wid * 2 + 1) * 72) * 128 + lane * 4;
    const float* wg0 = g_w1f + ((16 + wid * 2 + 0) * 72) * 128 + lane * 4;
    const float* wg1 = g_w1f + ((16 + wid * 2 + 1) * 72) * 128 + lane * 4;

    {
        int tt0 = tid4,     off0 = tid4;
        int tt1 = tid4 + 4, off1 = tid4 + 4;
        for (int kc = 0; kc < 72; kc++) {
            uint4 ah0 = *(const uint4*)(wf0 + kc * 128);
            uint4 ah1 = *(const uint4*)(wf1 + kc * 128);
            uint4 al0 = *(const uint4*)(wg0 + kc * 128);
            uint4 al1 = *(const uint4*)(wg1 + kc * 128);
            unsigned bb0[4], bb1[4];
#pragma unroll
            for (int nt = 0; nt < 4; nt++) {
                bb0[nt] = __float_as_uint(xbh[off0 + nt * 8 + group]);
                bb1[nt] = __float_as_uint(xbh[off1 + nt * 8 + group]);
            }
#pragma unroll
            for (int nt = 0; nt < 4; nt++) {
                MMA_TF32(c[0][nt], ah0, bb0[nt], bb1[nt]);
                MMA_TF32(c[1][nt], ah1, bb0[nt], bb1[nt]);
            }
#pragma unroll
            for (int nt = 0; nt < 4; nt++) {
                MMA_TF32(c[0][nt], al0, bb0[nt], bb1[nt]);
                MMA_TF32(c[1][nt], al1, bb0[nt], bb1[nt]);
            }
            tt0 += 8; if (tt0 >= 9) { tt0 -= 9; off0 += 47; } else off0 += 8;
            tt1 += 8; if (tt1 >= 9) { tt1 -= 9; off1 += 47; } else off1 += 8;
        }
    }
    {
        int tt0 = tid4,     off0 = tid4;
        int tt1 = tid4 + 4, off1 = tid4 + 4;
        for (int kc = 0; kc < 72; kc++) {
            uint4 ah0 = *(const uint4*)(wf0 + kc * 128);
            uint4 ah1 = *(const uint4*)(wf1 + kc * 128);
            unsigned bb0[4], bb1[4];
#pragma unroll
            for (int nt = 0; nt < 4; nt++) {
                bb0[nt] = __float_as_uint(xbl[off0 + nt * 8 + group]);
                bb1[nt] = __float_as_uint(xbl[off1 + nt * 8 + group]);
            }
#pragma unroll
            for (int nt = 0; nt < 4; nt++) {
                MMA_TF32(c[0][nt], ah0, bb0[nt], bb1[nt]);
                MMA_TF32(c[1][nt], ah1, bb0[nt], bb1[nt]);
            }
            tt0 += 8; if (tt0 >= 9) { tt0 -= 9; off0 += 47; } else off0 += 8;
            tt1 += 8; if (tt1 >= 9) { tt1 -= 9; off1 += 47; } else off1 += 8;
        }
    }
    __syncthreads();

#pragma unroll
    for (int mt = 0; mt < 2; mt++)
#pragma unroll
        for (int nt = 0; nt < 4; nt++)
#pragma unroll
            for (int i = 0; i < 4; i++) {
                int oc   = wid * 32 + mt * 16 + ((i >> 1) << 3) + group;
                int lloc = nt * 8 + tid4 * 2 + (i & 1);
                ysh[lloc][oc] = c[mt][nt][i] + b1s[oc];
            }
    __syncthreads();

    for (int g = t; g < 1024; g += 256) {
        int lloc = g >> 5, cp = g & 31;
        float4 a  = *(const float4*)&ysh[lloc][cp * 8];
        float4 c4 = *(const float4*)&ysh[lloc][cp * 8 + 4];
        float sq = (a.x * a.x + a.y * a.y) + (a.z * a.z + a.w * a.w)
                 + (c4.x * c4.x + c4.y * c4.y) + (c4.z * c4.z + c4.w * c4.w);
        float scale = sq / (1.f + sq) * rsqrtf(sq + 1e-8f);
        a.x *= scale; a.y *= scale; a.z *= scale; a.w *= scale;
        c4.x *= scale; c4.y *= scale; c4.z *= scale; c4.w *= scale;
        float* dst = &g_yq[((size_t)(b * L_ + l0 + lloc)) * NOC1 + cp * 8];
        *(float4*)dst       = a;
        *(float4*)(dst + 4) = c4;
    }
}

// ---------------------------------------------------------------------------
// Kernel 2: conv2 via tensor cores + routing (R13-verified), reg-pinned at
// 64 regs / 4 CTAs per SM — the measured occupancy sweet spot.
// ---------------------------------------------------------------------------
__global__ __launch_bounds__(256, 4) void conv2_route_kernel(
    const float* __restrict__ b2, float* __restrict__ out)
{
    __shared__ float yph[CP_][YPAD];
    __shared__ float ypl[CP_][YPAD];
    __shared__ float b2s[NOC1];
    __shared__ float efT[CSA_][EPAD];
    __shared__ __align__(16) float sinv[CP_];
    __shared__ float vsh[16][16];
    __shared__ __align__(16) float Vs[16][16][VPAD];

    const int bl = blockIdx.x;
    const int l  = bl & (L_ - 1);
    const int t  = threadIdx.x;
    const int wid   = t >> 5;
    const int lane  = t & 31;
    const int group = lane >> 2;
    const int tid4  = lane & 3;

    {
        const float* base = g_yq + (size_t)bl * NOC1;
        const int cp_i = t >> 3, j_i = t & 7;
#pragma unroll
        for (int dh = 0; dh < 3; dh++) {
            float val = 0.f;
            if ((dh == 1) || (dh == 0 && l > 0) || (dh == 2 && l < L_ - 1))
                val = base[t + (dh - 1) * NOC1];
            float hi = t32hi(val);
            yph[cp_i][dh * 8 + j_i] = hi;
            ypl[cp_i][dh * 8 + j_i] = val - hi;
        }
        b2s[t] = b2[t];
    }
    __syncthreads();

    float c[2][4][4];
#pragma unroll
    for (int mt = 0; mt < 2; mt++) {
        float bv0 = b2s[wid * 32 + mt * 16 + group];
        float bv1 = b2s[wid * 32 + mt * 16 + 8 + group];
#pragma unroll
        for (int nt = 0; nt < 4; nt++) {
            c[mt][nt][0] = bv0; c[mt][nt][1] = bv0;
            c[mt][nt][2] = bv1; c[mt][nt][3] = bv1;
        }
    }

    uint4 af[2][3];
#pragma unroll
    for (int mt = 0; mt < 2; mt++)
#pragma unroll
        for (int k = 0; k < 3; k++)
            af[mt][k] = *(const uint4*)&g_w2f[(((wid * 2 + mt)) * 3 + k) * 128 + lane * 4];

#pragma unroll
    for (int pass = 0; pass < 2; pass++) {
        const float (*yp)[YPAD] = pass ? ypl : yph;
#pragma unroll
        for (int k = 0; k < 3; k++)
#pragma unroll
            for (int nt = 0; nt < 4; nt++) {
                unsigned b0 = __float_as_uint(yp[nt * 8 + group][k * 8 + tid4]);
                unsigned b1 = __float_as_uint(yp[nt * 8 + group][k * 8 + tid4 + 4]);
                MMA_TF32(c[0][nt], af[0][k], b0, b1);
                MMA_TF32(c[1][nt], af[1][k], b0, b1);
            }
    }
#pragma unroll
    for (int mt = 0; mt < 2; mt++)
#pragma unroll
        for (int k = 0; k < 3; k++)
            af[mt][k] = *(const uint4*)&g_w2f[((16 + wid * 2 + mt) * 3 + k) * 128 + lane * 4];
#pragma unroll
    for (int k = 0; k < 3; k++)
#pragma unroll
        for (int nt = 0; nt < 4; nt++) {
            unsigned b0 = __float_as_uint(yph[nt * 8 + group][k * 8 + tid4]);
            unsigned b1 = __float_as_uint(yph[nt * 8 + group][k * 8 + tid4 + 4]);
            MMA_TF32(c[0][nt], af[0][k], b0, b1);
            MMA_TF32(c[1][nt], af[1][k], b0, b1);
        }

#pragma unroll
    for (int mt = 0; mt < 2; mt++) {
        int csaw = wid * 2 + mt;
#pragma unroll
        for (int nt = 0; nt < 4; nt++) {
            int cp0 = nt * 8 + tid4 * 2;
            *(float2*)&Vs[csaw][group][cp0]     = make_float2(c[mt][nt][0], c[mt][nt][1]);
            *(float2*)&Vs[csaw][group + 8][cp0] = make_float2(c[mt][nt][2], c[mt][nt][3]);
        }
    }
    __syncthreads();

    const int csa = t >> 4;
    const int asa = t & 15;
    const ulonglong2* Vp = (const ulonglong2*)&Vs[csa][asa][0];

    float v;
    {
        const float4* vr = (const float4*)&Vs[csa][asa][0];
        float4 r0 = vr[0], r1 = vr[1], r2 = vr[2], r3 = vr[3];
        float4 r4 = vr[4], r5 = vr[5], r6 = vr[6], r7 = vr[7];
        float s0 = (r0.x + r0.y) + (r0.z + r0.w) + (r4.x + r4.y) + (r4.z + r4.w);
        float s1 = (r1.x + r1.y) + (r1.z + r1.w) + (r5.x + r5.y) + (r5.z + r5.w);
        float s2 = (r2.x + r2.y) + (r2.z + r2.w) + (r6.x + r6.y) + (r6.z + r6.w);
        float s3 = (r3.x + r3.y) + (r3.z + r3.w) + (r7.x + r7.y) + (r7.z + r7.w);
        float s = ((s0 + s1) + (s2 + s3)) * (1.f / 16.f);
        float sq = s * s;
        sq += __shfl_xor_sync(0xffffffffu, sq, 1);
        sq += __shfl_xor_sync(0xffffffffu, sq, 2);
        sq += __shfl_xor_sync(0xffffffffu, sq, 4);
        sq += __shfl_xor_sync(0xffffffffu, sq, 8);
        float scale = sq / (1.f + sq) * rsqrtf(sq + 1e-8f);
        v = s * scale;
    }
    vsh[csa][asa] = v;
    __syncthreads();

    const int cp_a = t & 31;
    const int cs0  = t >> 5;
    float blog0, blog1;
    {
        const float4* vpA = (const float4*)vsh[cs0];
        const float4* vpB = (const float4*)vsh[cs0 + 8];
        float4 vA0 = vpA[0], vA1 = vpA[1], vA2 = vpA[2], vA3 = vpA[3];
        float4 vB0 = vpB[0], vB1 = vpB[1], vB2 = vpB[2], vB3 = vpB[3];
        const float* VsA = &Vs[cs0][0][cp_a];
        const float* VsB = &Vs[cs0 + 8][0][cp_a];
        float p0, p1, q0, q1;
        p0  = VsA[0*VPAD]*vA0.x + VsA[1*VPAD]*vA0.y + VsA[2*VPAD]*vA0.z + VsA[3*VPAD]*vA0.w;
        p1  = VsA[4*VPAD]*vA1.x + VsA[5*VPAD]*vA1.y + VsA[6*VPAD]*vA1.z + VsA[7*VPAD]*vA1.w;
        p0 += VsA[8*VPAD]*vA2.x + VsA[9*VPAD]*vA2.y + VsA[10*VPAD]*vA2.z + VsA[11*VPAD]*vA2.w;
        p1 += VsA[12*VPAD]*vA3.x + VsA[13*VPAD]*vA3.y + VsA[14*VPAD]*vA3.z + VsA[15*VPAD]*vA3.w;
        q0  = VsB[0*VPAD]*vB0.x + VsB[1*VPAD]*vB0.y + VsB[2*VPAD]*vB0.z + VsB[3*VPAD]*vB0.w;
        q1  = VsB[4*VPAD]*vB1.x + VsB[5*VPAD]*vB1.y + VsB[6*VPAD]*vB1.z + VsB[7*VPAD]*vB1.w;
        q0 += VsB[8*VPAD]*vB2.x + VsB[9*VPAD]*vB2.y + VsB[10*VPAD]*vB2.z + VsB[11*VPAD]*vB2.w;
        q1 += VsB[12*VPAD]*vB3.x + VsB[13*VPAD]*vB3.y + VsB[14*VPAD]*vB3.z + VsB[15*VPAD]*vB3.w;
        blog0 = p0 + p1;
        blog1 = q0 + q1;
    }

#pragma unroll
    for (int r = 1; r < 3; r++) {
        efT[cs0][cp_a]     = __expf(blog0);
        efT[cs0 + 8][cp_a] = __expf(blog1);
        __syncthreads();
        if (t < CP_) {
            float u0 = 0.f, u1 = 0.f, u2 = 0.f, u3 = 0.f;
#pragma unroll
            for (int j2 = 0; j2 < CSA_; j2 += 4) {
                u0 += efT[j2][t];     u1 += efT[j2 + 1][t];
                u2 += efT[j2 + 2][t]; u3 += efT[j2 + 3][t];
            }
            sinv[t] = __fdividef(1.f, (u0 + u1) + (u2 + u3));
        }
        __syncthreads();

        ull s2a = 0ULL, s2b = 0ULL, s2c = 0ULL, s2d = 0ULL;
        const ulonglong2* efp = (const ulonglong2*)&efT[csa][0];
        const ulonglong2* svp = (const ulonglong2*)sinv;
#pragma unroll
        for (int q = 0; q < 8; q++) {
            ulonglong2 e2 = efp[q];
            ulonglong2 n2 = svp[q];
            ulonglong2 v2 = Vp[q];
            ull p0, p1;
            MUL2(p0, e2.x, n2.x);
            MUL2(p1, e2.y, n2.y);
            if (q & 1) {
                FFMA2(s2c, p0, v2.x);
                FFMA2(s2d, p1, v2.y);
            } else {
                FFMA2(s2a, p0, v2.x);
                FFMA2(s2b, p1, v2.y);
            }
        }
        ADD2(s2a, s2a, s2b);
        ADD2(s2c, s2c, s2d);
        ADD2(s2a, s2a, s2c);
        float lo, hi;
        UNPACK2(lo, hi, s2a);
        float s = lo + hi;

        float sq = s * s;
        sq += __shfl_xor_sync(0xffffffffu, sq, 1);
        sq += __shfl_xor_sync(0xffffffffu, sq, 2);
        sq += __shfl_xor_sync(0xffffffffu, sq, 4);
        sq += __shfl_xor_sync(0xffffffffu, sq, 8);
        float scale = sq / (1.f + sq) * rsqrtf(sq + 1e-8f);
        v = s * scale;

        if (r < 2) {
            vsh[csa][asa] = v;
            __syncthreads();
            const float4* vpA = (const float4*)vsh[cs0];
            const float4* vpB = (const float4*)vsh[cs0 + 8];
            float4 vA0 = vpA[0], vA1 = vpA[1], vA2 = vpA[2], vA3 = vpA[3];
            float4 vB0 = vpB[0], vB1 = vpB[1], vB2 = vpB[2], vB3 = vpB[3];
            const float* VsA = &Vs[cs0][0][cp_a];
            const float* VsB = &Vs[cs0 + 8][0][cp_a];
            float p0, p1, q0, q1;
            p0  = VsA[0*VPAD]*vA0.x + VsA[1*VPAD]*vA0.y + VsA[2*VPAD]*vA0.z + VsA[3*VPAD]*vA0.w;
            p1  = VsA[4*VPAD]*vA1.x + VsA[5*VPAD]*vA1.y + VsA[6*VPAD]*vA1.z + VsA[7*VPAD]*vA1.w;
            p0 += VsA[8*VPAD]*vA2.x + VsA[9*VPAD]*vA2.y + VsA[10*VPAD]*vA2.z + VsA[11*VPAD]*vA2.w;
            p1 += VsA[12*VPAD]*vA3.x + VsA[13*VPAD]*vA3.y + VsA[14*VPAD]*vA3.z + VsA[15*VPAD]*vA3.w;
            q0  = VsB[0*VPAD]*vB0.x + VsB[1*VPAD]*vB0.y + VsB[2*VPAD]*vB0.z + VsB[3*VPAD]*vB0.w;
            q1  = VsB[4*VPAD]*vB1.x + VsB[5*VPAD]*vB1.y + VsB[6*VPAD]*vB1.z + VsB[7*VPAD]*vB1.w;
            q0 += VsB[8*VPAD]*vB2.x + VsB[9*VPAD]*vB2.y + VsB[10*VPAD]*vB2.z + VsB[11*VPAD]*vB2.w;
            q1 += VsB[12*VPAD]*vB3.x + VsB[13*VPAD]*vB3.y + VsB[14*VPAD]*vB3.z + VsB[15*VPAD]*vB3.w;
            blog0 += p0 + p1;
            blog1 += q0 + q1;
        }
    }

    out[(size_t)bl * 256 + t] = v;
}

// ---------------------------------------------------------------------------
extern "C" void kernel_launch(void* const* d_in, const int* in_sizes, int n_in,
                              void* d_out, int out_size)
{
    const float* x  = (const float*)d_in[0];
    const float* w1 = (const float*)d_in[1];
    const float* b1 = (const float*)d_in[2];
    const float* w2 = (const float*)d_in[3];
    const float* b2 = (const float*)d_in[4];
    float* out = (float*)d_out;

    prep_kernel<<<1152, 256>>>(w1, w2);
    conv1_mma_kernel<<<dim3(L_ / 32, B_), 256>>>(x, b1);
    conv2_route_kernel<<<B_ * L_, 256>>>(b2, out);
}

// round 17
// speedup vs baseline: 1.7480x; 1.1564x over previous
#include <cuda_runtime.h>

// Problem constants
#define B_    8
#define K_    64
#define L_    1024
#define CP_   32
#define CSA_  16
#define NOC1  256
#define K1    576          // K_*G2_
#define VPAD  36
#define EPAD  36
#define YPAD  28

typedef unsigned long long ull;

#define FFMA2(acc, a, b) asm("fma.rn.f32x2 %0, %1, %2, %0;" : "+l"(acc) : "l"(a), "l"(b))
#define MUL2(dst, a, b)  asm("mul.rn.f32x2 %0, %1, %2;" : "=l"(dst) : "l"(a), "l"(b))
#define ADD2(dst, a, b)  asm("add.rn.f32x2 %0, %1, %2;" : "=l"(dst) : "l"(a), "l"(b))
#define UNPACK2(lo, hi, v) asm("mov.b64 {%0, %1}, %2;" : "=f"(lo), "=f"(hi) : "l"(v))

#define MMA_TF32(c, au, b0, b1) \
    asm("mma.sync.aligned.m16n8k8.row.col.f32.tf32.tf32.f32 " \
        "{%0,%1,%2,%3},{%4,%5,%6,%7},{%8,%9},{%0,%1,%2,%3};" \
        : "+f"((c)[0]), "+f"((c)[1]), "+f"((c)[2]), "+f"((c)[3]) \
        : "r"((au).x), "r"((au).y), "r"((au).z), "r"((au).w), "r"(b0), "r"(b1))

__device__ __forceinline__ float t32hi(float x) {
    return __uint_as_float(__float_as_uint(x) & 0xFFFFE000u);
}

// Scratch (allocation-free: device globals)
__device__ float g_yq[B_ * L_ * NOC1];
__device__ float g_w1f[2 * 16 * 72 * 128];
__device__ float g_w2f[2 * 16 * 3 * 128];

// ---------------------------------------------------------------------------
// Prep: build tf32 hi/lo weight fragments for conv1 and conv2
// ---------------------------------------------------------------------------
__global__ void prep_kernel(const float* __restrict__ w1, const float* __restrict__ w2) {
    int idx = blockIdx.x * 256 + threadIdx.x;
    if (idx < 2 * 16 * 72 * 128) {
        int i    = idx & 3;
        int lane = (idx >> 2) & 31;
        int rest = idx >> 7;
        int kc    = rest % 72;
        int mtf   = (rest / 72) & 15;
        int split = rest / 1152;
        int group = lane >> 2, tid4 = lane & 3;
        int row = mtf * 16 + ((i & 1) << 3) + group;
        int col = kc * 8 + ((i >> 1) << 2) + tid4;
        float val = w1[row * K1 + col];
        float hi = t32hi(val);
        g_w1f[idx] = split ? (val - hi) : hi;
    }
    if (idx < 2 * 16 * 3 * 128) {
        int i    = idx & 3;
        int lane = (idx >> 2) & 31;
        int rest = idx >> 7;
        int k    = rest % 3;
        int mt   = (rest / 3) & 15;
        int split = rest / 48;
        int group = lane >> 2, tid4 = lane & 3;
        int row = ((i & 1) << 3) + group;
        int col = ((i >> 1) << 2) + tid4;
        float val = w2[(mt * 16 + row) * 24 + k * 8 + col];
        float hi = t32hi(val);
        g_w2f[idx] = split ? (val - hi) : hi;
    }
}

// ---------------------------------------------------------------------------
// Kernel 1: conv1 via tensor cores (m16n8k8 tf32, 3-term split) + squash.
// ---------------------------------------------------------------------------
__global__ __launch_bounds__(256) void conv1_mma_kernel(
    const float* __restrict__ x, const float* __restrict__ b1)
{
    __shared__ __align__(16) float sbuf[32 * 264];
    __shared__ float b1s[NOC1];
    float (*xh)[48]  = (float(*)[48])sbuf;
    float (*xl)[48]  = (float(*)[48])(sbuf + 64 * 48);
    float (*ysh)[264] = (float(*)[264])sbuf;

    const int b  = blockIdx.y;
    const int l0 = blockIdx.x * 32;
    const int t  = threadIdx.x;

    b1s[t] = b1[t];
    for (int i = t; i < K_ * 40; i += 256) {
        int ic = i / 40, j = i - ic * 40;
        int l = l0 - 4 + j;
        float v = (l >= 0 && l < L_) ? x[(b * K_ + ic) * L_ + l] : 0.f;
        float hi = t32hi(v);
        xh[ic][j] = hi;
        xl[ic][j] = v - hi;
    }
    __syncthreads();

    const int wid = t >> 5, lane = t & 31;
    const int group = lane >> 2, tid4 = lane & 3;

    float c[2][4][4];
#pragma unroll
    for (int mt = 0; mt < 2; mt++)
#pragma unroll
        for (int nt = 0; nt < 4; nt++)
#pragma unroll
            for (int i = 0; i < 4; i++) c[mt][nt][i] = 0.f;

    const float* xbh = &xh[0][0];
    const float* xbl = &xl[0][0];
    const float* wf0 = g_w1f + ((wid * 2 + 0) * 72) * 128 + lane * 4;
    const float* wf1 = g_w1f + ((wid * 2 + 1) * 72) * 128 + lane * 4;
    const float* wg0 = g_w1f + ((16 + wid * 2 + 0) * 72) * 128 + lane * 4;
    const float* wg1 = g_w1f + ((16 + wid * 2 + 1) * 72) * 128 + lane * 4;

    {
        int tt0 = tid4,     off0 = tid4;
        int tt1 = tid4 + 4, off1 = tid4 + 4;
        for (int kc = 0; kc < 72; kc++) {
            uint4 ah0 = *(const uint4*)(wf0 + kc * 128);
            uint4 ah1 = *(const uint4*)(wf1 + kc * 128);
            uint4 al0 = *(const uint4*)(wg0 + kc * 128);
            uint4 al1 = *(const uint4*)(wg1 + kc * 128);
            unsigned bb0[4], bb1[4];
#pragma unroll
            for (int nt = 0; nt < 4; nt++) {
                bb0[nt] = __float_as_uint(xbh[off0 + nt * 8 + group]);
                bb1[nt] = __float_as_uint(xbh[off1 + nt * 8 + group]);
            }
#pragma unroll
            for (int nt = 0; nt < 4; nt++) {
                MMA_TF32(c[0][nt], ah0, bb0[nt], bb1[nt]);
                MMA_TF32(c[1][nt], ah1, bb0[nt], bb1[nt]);
            }
#pragma unroll
            for (int nt = 0; nt < 4; nt++) {
                MMA_TF32(c[0][nt], al0, bb0[nt], bb1[nt]);
                MMA_TF32(c[1][nt], al1, bb0[nt], bb1[nt]);
            }
            tt0 += 8; if (tt0 >= 9) { tt0 -= 9; off0 += 47; } else off0 += 8;
            tt1 += 8; if (tt1 >= 9) { tt1 -= 9; off1 += 47; } else off1 += 8;
        }
    }
    {
        int tt0 = tid4,     off0 = tid4;
        int tt1 = tid4 + 4, off1 = tid4 + 4;
        for (int kc = 0; kc < 72; kc++) {
            uint4 ah0 = *(const uint4*)(wf0 + kc * 128);
            uint4 ah1 = *(const uint4*)(wf1 + kc * 128);
            unsigned bb0[4], bb1[4];
#pragma unroll
            for (int nt = 0; nt < 4; nt++) {
                bb0[nt] = __float_as_uint(xbl[off0 + nt * 8 + group]);
                bb1[nt] = __float_as_uint(xbl[off1 + nt * 8 + group]);
            }
#pragma unroll
            for (int nt = 0; nt < 4; nt++) {
                MMA_TF32(c[0][nt], ah0, bb0[nt], bb1[nt]);
                MMA_TF32(c[1][nt], ah1, bb0[nt], bb1[nt]);
            }
            tt0 += 8; if (tt0 >= 9) { tt0 -= 9; off0 += 47; } else off0 += 8;
            tt1 += 8; if (tt1 >= 9) { tt1 -= 9; off1 += 47; } else off1 += 8;
        }
    }
    __syncthreads();

#pragma unroll
    for (int mt = 0; mt < 2; mt++)
#pragma unroll
        for (int nt = 0; nt < 4; nt++)
#pragma unroll
            for (int i = 0; i < 4; i++) {
                int oc   = wid * 32 + mt * 16 + ((i >> 1) << 3) + group;
                int lloc = nt * 8 + tid4 * 2 + (i & 1);
                ysh[lloc][oc] = c[mt][nt][i] + b1s[oc];
            }
    __syncthreads();

    for (int g = t; g < 1024; g += 256) {
        int lloc = g >> 5, cp = g & 31;
        float4 a  = *(const float4*)&ysh[lloc][cp * 8];
        float4 c4 = *(const float4*)&ysh[lloc][cp * 8 + 4];
        float sq = (a.x * a.x + a.y * a.y) + (a.z * a.z + a.w * a.w)
                 + (c4.x * c4.x + c4.y * c4.y) + (c4.z * c4.z + c4.w * c4.w);
        float scale = sq / (1.f + sq) * rsqrtf(sq + 1e-8f);
        a.x *= scale; a.y *= scale; a.z *= scale; a.w *= scale;
        c4.x *= scale; c4.y *= scale; c4.z *= scale; c4.w *= scale;
        float* dst = &g_yq[((size_t)(b * L_ + l0 + lloc)) * NOC1 + cp * 8];
        *(float4*)dst       = a;
        *(float4*)(dst + 4) = c4;
    }
}

// ---------------------------------------------------------------------------
// Kernel 2: conv2 via tensor cores + routing (R13-exact, no reg constraints)
// ---------------------------------------------------------------------------
__global__ __launch_bounds__(256) void conv2_route_kernel(
    const float* __restrict__ b2, float* __restrict__ out)
{
    __shared__ float yph[CP_][YPAD];
    __shared__ float ypl[CP_][YPAD];
    __shared__ float b2s[NOC1];
    __shared__ float efT[CSA_][EPAD];
    __shared__ __align__(16) float sinv[CP_];
    __shared__ float vsh[16][16];
    __shared__ __align__(16) float Vs[16][16][VPAD];

    const int bl = blockIdx.x;
    const int l  = bl & (L_ - 1);
    const int t  = threadIdx.x;
    const int wid   = t >> 5;
    const int lane  = t & 31;
    const int group = lane >> 2;
    const int tid4  = lane & 3;

    {
        const float* base = g_yq + (size_t)bl * NOC1;
        const int cp_i = t >> 3, j_i = t & 7;
#pragma unroll
        for (int dh = 0; dh < 3; dh++) {
            float val = 0.f;
            if ((dh == 1) || (dh == 0 && l > 0) || (dh == 2 && l < L_ - 1))
                val = base[t + (dh - 1) * NOC1];
            float hi = t32hi(val);
            yph[cp_i][dh * 8 + j_i] = hi;
            ypl[cp_i][dh * 8 + j_i] = val - hi;
        }
        b2s[t] = b2[t];
    }
    __syncthreads();

    float c[2][4][4];
#pragma unroll
    for (int mt = 0; mt < 2; mt++) {
        float bv0 = b2s[wid * 32 + mt * 16 + group];
        float bv1 = b2s[wid * 32 + mt * 16 + 8 + group];
#pragma unroll
        for (int nt = 0; nt < 4; nt++) {
            c[mt][nt][0] = bv0; c[mt][nt][1] = bv0;
            c[mt][nt][2] = bv1; c[mt][nt][3] = bv1;
        }
    }

    uint4 af[2][3];
#pragma unroll
    for (int mt = 0; mt < 2; mt++)
#pragma unroll
        for (int k = 0; k < 3; k++)
            af[mt][k] = *(const uint4*)&g_w2f[(((wid * 2 + mt)) * 3 + k) * 128 + lane * 4];

#pragma unroll
    for (int pass = 0; pass < 2; pass++) {
        const float (*yp)[YPAD] = pass ? ypl : yph;
#pragma unroll
        for (int k = 0; k < 3; k++)
#pragma unroll
            for (int nt = 0; nt < 4; nt++) {
                unsigned b0 = __float_as_uint(yp[nt * 8 + group][k * 8 + tid4]);
                unsigned b1 = __float_as_uint(yp[nt * 8 + group][k * 8 + tid4 + 4]);
                MMA_TF32(c[0][nt], af[0][k], b0, b1);
                MMA_TF32(c[1][nt], af[1][k], b0, b1);
            }
    }
#pragma unroll
    for (int mt = 0; mt < 2; mt++)
#pragma unroll
        for (int k = 0; k < 3; k++)
            af[mt][k] = *(const uint4*)&g_w2f[((16 + wid * 2 + mt) * 3 + k) * 128 + lane * 4];
#pragma unroll
    for (int k = 0; k < 3; k++)
#pragma unroll
        for (int nt = 0; nt < 4; nt++) {
            unsigned b0 = __float_as_uint(yph[nt * 8 + group][k * 8 + tid4]);
            unsigned b1 = __float_as_uint(yph[nt * 8 + group][k * 8 + tid4 + 4]);
            MMA_TF32(c[0][nt], af[0][k], b0, b1);
            MMA_TF32(c[1][nt], af[1][k], b0, b1);
        }

#pragma unroll
    for (int mt = 0; mt < 2; mt++) {
        int csaw = wid * 2 + mt;
#pragma unroll
        for (int nt = 0; nt < 4; nt++) {
            int cp0 = nt * 8 + tid4 * 2;
            *(float2*)&Vs[csaw][group][cp0]     = make_float2(c[mt][nt][0], c[mt][nt][1]);
            *(float2*)&Vs[csaw][group + 8][cp0] = make_float2(c[mt][nt][2], c[mt][nt][3]);
        }
    }
    __syncthreads();

    const int csa = t >> 4;
    const int asa = t & 15;
    const ulonglong2* Vp = (const ulonglong2*)&Vs[csa][asa][0];

    float v;
    {
        const float4* vr = (const float4*)&Vs[csa][asa][0];
        float4 r0 = vr[0], r1 = vr[1], r2 = vr[2], r3 = vr[3];
        float4 r4 = vr[4], r5 = vr[5], r6 = vr[6], r7 = vr[7];
        float s0 = (r0.x + r0.y) + (r0.z + r0.w) + (r4.x + r4.y) + (r4.z + r4.w);
        float s1 = (r1.x + r1.y) + (r1.z + r1.w) + (r5.x + r5.y) + (r5.z + r5.w);
        float s2 = (r2.x + r2.y) + (r2.z + r2.w) + (r6.x + r6.y) + (r6.z + r6.w);
        float s3 = (r3.x + r3.y) + (r3.z + r3.w) + (r7.x + r7.y) + (r7.z + r7.w);
        float s = ((s0 + s1) + (s2 + s3)) * (1.f / 16.f);
        float sq = s * s;
        sq += __shfl_xor_sync(0xffffffffu, sq, 1);
        sq += __shfl_xor_sync(0xffffffffu, sq, 2);
        sq += __shfl_xor_sync(0xffffffffu, sq, 4);
        sq += __shfl_xor_sync(0xffffffffu, sq, 8);
        float scale = sq / (1.f + sq) * rsqrtf(sq + 1e-8f);
        v = s * scale;
    }
    vsh[csa][asa] = v;
    __syncthreads();

    const int cp_a = t & 31;
    const int cs0  = t >> 5;
    float blog0, blog1;
    {
        const float4* vpA = (const float4*)vsh[cs0];
        const float4* vpB = (const float4*)vsh[cs0 + 8];
        float4 vA0 = vpA[0], vA1 = vpA[1], vA2 = vpA[2], vA3 = vpA[3];
        float4 vB0 = vpB[0], vB1 = vpB[1], vB2 = vpB[2], vB3 = vpB[3];
        const float* VsA = &Vs[cs0][0][cp_a];
        const float* VsB = &Vs[cs0 + 8][0][cp_a];
        float p0, p1, q0, q1;
        p0  = VsA[0*VPAD]*vA0.x + VsA[1*VPAD]*vA0.y + VsA[2*VPAD]*vA0.z + VsA[3*VPAD]*vA0.w;
        p1  = VsA[4*VPAD]*vA1.x + VsA[5*VPAD]*vA1.y + VsA[6*VPAD]*vA1.z + VsA[7*VPAD]*vA1.w;
        p0 += VsA[8*VPAD]*vA2.x + VsA[9*VPAD]*vA2.y + VsA[10*VPAD]*vA2.z + VsA[11*VPAD]*vA2.w;
        p1 += VsA[12*VPAD]*vA3.x + VsA[13*VPAD]*vA3.y + VsA[14*VPAD]*vA3.z + VsA[15*VPAD]*vA3.w;
        q0  = VsB[0*VPAD]*vB0.x + VsB[1*VPAD]*vB0.y + VsB[2*VPAD]*vB0.z + VsB[3*VPAD]*vB0.w;
        q1  = VsB[4*VPAD]*vB1.x + VsB[5*VPAD]*vB1.y + VsB[6*VPAD]*vB1.z + VsB[7*VPAD]*vB1.w;
        q0 += VsB[8*VPAD]*vB2.x + VsB[9*VPAD]*vB2.y + VsB[10*VPAD]*vB2.z + VsB[11*VPAD]*vB2.w;
        q1 += VsB[12*VPAD]*vB3.x + VsB[13*VPAD]*vB3.y + VsB[14*VPAD]*vB3.z + VsB[15*VPAD]*vB3.w;
        blog0 = p0 + p1;
        blog1 = q0 + q1;
    }

#pragma unroll
    for (int r = 1; r < 3; r++) {
        efT[cs0][cp_a]     = __expf(blog0);
        efT[cs0 + 8][cp_a] = __expf(blog1);
        __syncthreads();
        if (t < CP_) {
            float u0 = 0.f, u1 = 0.f, u2 = 0.f, u3 = 0.f;
#pragma unroll
            for (int j2 = 0; j2 < CSA_; j2 += 4) {
                u0 += efT[j2][t];     u1 += efT[j2 + 1][t];
                u2 += efT[j2 + 2][t]; u3 += efT[j2 + 3][t];
            }
            sinv[t] = __fdividef(1.f, (u0 + u1) + (u2 + u3));
        }
        __syncthreads();

        ull s2a = 0ULL, s2b = 0ULL, s2c = 0ULL, s2d = 0ULL;
        const ulonglong2* efp = (const ulonglong2*)&efT[csa][0];
        const ulonglong2* svp = (const ulonglong2*)sinv;
#pragma unroll
        for (int q = 0; q < 8; q++) {
            ulonglong2 e2 = efp[q];
            ulonglong2 n2 = svp[q];
            ulonglong2 v2 = Vp[q];
            ull p0, p1;
            MUL2(p0, e2.x, n2.x);
            MUL2(p1, e2.y, n2.y);
            if (q & 1) {
                FFMA2(s2c, p0, v2.x);
                FFMA2(s2d, p1, v2.y);
            } else {
                FFMA2(s2a, p0, v2.x);
                FFMA2(s2b, p1, v2.y);
            }
        }
        ADD2(s2a, s2a, s2b);
        ADD2(s2c, s2c, s2d);
        ADD2(s2a, s2a, s2c);
        float lo, hi;
        UNPACK2(lo, hi, s2a);
        float s = lo + hi;

        float sq = s * s;
        sq += __shfl_xor_sync(0xffffffffu, sq, 1);
        sq += __shfl_xor_sync(0xffffffffu, sq, 2);
        sq += __shfl_xor_sync(0xffffffffu, sq, 4);
        sq += __shfl_xor_sync(0xffffffffu, sq, 8);
        float scale = sq / (1.f + sq) * rsqrtf(sq + 1e-8f);
        v = s * scale;

        if (r < 2) {
            vsh[csa][asa] = v;
            __syncthreads();
            const float4* vpA = (const float4*)vsh[cs0];
            const float4* vpB = (const float4*)vsh[cs0 + 8];
            float4 vA0 = vpA[0], vA1 = vpA[1], vA2 = vpA[2], vA3 = vpA[3];
            float4 vB0 = vpB[0], vB1 = vpB[1], vB2 = vpB[2], vB3 = vpB[3];
            const float* VsA = &Vs[cs0][0][cp_a];
            const float* VsB = &Vs[cs0 + 8][0][cp_a];
            float p0, p1, q0, q1;
            p0  = VsA[0*VPAD]*vA0.x + VsA[1*VPAD]*vA0.y + VsA[2*VPAD]*vA0.z + VsA[3*VPAD]*vA0.w;
            p1  = VsA[4*VPAD]*vA1.x + VsA[5*VPAD]*vA1.y + VsA[6*VPAD]*vA1.z + VsA[7*VPAD]*vA1.w;
            p0 += VsA[8*VPAD]*vA2.x + VsA[9*VPAD]*vA2.y + VsA[10*VPAD]*vA2.z + VsA[11*VPAD]*vA2.w;
            p1 += VsA[12*VPAD]*vA3.x + VsA[13*VPAD]*vA3.y + VsA[14*VPAD]*vA3.z + VsA[15*VPAD]*vA3.w;
            q0  = VsB[0*VPAD]*vB0.x + VsB[1*VPAD]*vB0.y + VsB[2*VPAD]*vB0.z + VsB[3*VPAD]*vB0.w;
            q1  = VsB[4*VPAD]*vB1.x + VsB[5*VPAD]*vB1.y + VsB[6*VPAD]*vB1.z + VsB[7*VPAD]*vB1.w;
            q0 += VsB[8*VPAD]*vB2.x + VsB[9*VPAD]*vB2.y + VsB[10*VPAD]*vB2.z + VsB[11*VPAD]*vB2.w;
            q1 += VsB[12*VPAD]*vB3.x + VsB[13*VPAD]*vB3.y + VsB[14*VPAD]*vB3.z + VsB[15*VPAD]*vB3.w;
            blog0 += p0 + p1;
            blog1 += q0 + q1;
        }
    }

    out[(size_t)bl * 256 + t] = v;
}

// ---------------------------------------------------------------------------
extern "C" void kernel_launch(void* const* d_in, const int* in_sizes, int n_in,
                              void* d_out, int out_size)
{
    const float* x  = (const float*)d_in[0];
    const float* w1 = (const float*)d_in[1];
    const float* b1 = (const float*)d_in[2];
    const float* w2 = (const float*)d_in[3];
    const float* b2 = (const float*)d_in[4];
    float* out = (float*)d_out;

    prep_kernel<<<1152, 256>>>(w1, w2);
    conv1_mma_kernel<<<dim3(L_ / 32, B_), 256>>>(x, b1);
    conv2_route_kernel<<<B_ * L_, 256>>>(b2, out);
}